// round 11
// baseline (speedup 1.0000x reference)
#include <cuda_runtime.h>

// RadarNet R11: two kernels.
// K1: one warp per row, 128-thread blocks; diagonal scan fully unrolled with
//     predication (breaks the serial LDS->FMA chain).
// K2: 4 rows/warp static Jacobi with per-pair rotation dedup (R10-proven),
//     64-thread blocks for wave balance.

namespace {
constexpr int   TLEN = 512;
constexpr int   WINW = 20;
constexpr int   NW   = 493;
constexpr int   MAXB = 8192;
}

__device__ float g_S2[MAXB * 64];

// ---------------------------------------------------------------------------
// Kernel 1: covariance + S2, one warp per row, 4 warps/block
// ---------------------------------------------------------------------------
__global__ __launch_bounds__(128)
void radar_cov_kernel(const float* __restrict__ gx,
                      const float* __restrict__ gW1,
                      const float* __restrict__ gW2)
{
    __shared__ float W1s[320], W2s[128], Gs[160];
    __shared__ __align__(16) float xs[4][544];
    __shared__ float Cm[4][WINW][WINW + 1];
    __shared__ float Tgs[4][160];
    __shared__ float lagS[4][24];
    __shared__ float mwS[4][WINW];

    const int tid = threadIdx.x, wp = tid >> 5, l = tid & 31;
    const int b = blockIdx.x * 4 + wp;
    const unsigned FULL = 0xffffffffu;

    // ---- per-warp x load ----
    {
        const float4* gx4 = reinterpret_cast<const float4*>(gx + b * TLEN);
        float4* xs4 = reinterpret_cast<float4*>(xs[wp]);
        #pragma unroll
        for (int q = 0; q < 4; ++q) xs4[l + 32 * q] = gx4[l + 32 * q];
        if (l < 8) xs4[128 + l] = make_float4(0.f, 0.f, 0.f, 0.f);
    }

    // ---- block-cooperative weights + G = W1@W2 ----
    for (int i = tid; i < 320; i += 128) W1s[i] = gW1[i];
    if (tid < 128) W2s[tid] = gW2[tid];
    __syncthreads();
    for (int t = tid; t < 160; t += 128) {
        int w = t >> 3, c = t & 7;
        float s = 0.f;
        #pragma unroll
        for (int k = 0; k < 16; ++k) s = fmaf(W1s[w * 16 + k], W2s[k * 8 + c], s);
        Gs[t] = s;
    }
    __syncthreads();

    // ---- lag accumulation: lane l handles n in [16l, 16l+16) ----
    float xv[36];
    {
        const float4* base = reinterpret_cast<const float4*>(xs[wp] + 16 * l);
        #pragma unroll
        for (int q = 0; q < 9; ++q) {
            float4 t = base[q];
            xv[4*q+0] = t.x; xv[4*q+1] = t.y; xv[4*q+2] = t.z; xv[4*q+3] = t.w;
        }
    }
    float acc[21];
    #pragma unroll
    for (int d = 0; d < 21; ++d) acc[d] = 0.f;
    {
        const int nb = 16 * l;
        #pragma unroll
        for (int k = 0; k < 16; ++k) {
            if (nb + k < NW) {
                float xk = xv[k];
                #pragma unroll
                for (int d = 0; d < WINW; ++d) acc[d] = fmaf(xk, xv[k + d], acc[d]);
                acc[20] += xk;
            }
        }
    }
    #pragma unroll
    for (int d = 0; d < 21; ++d) {
        float v = acc[d];
        #pragma unroll
        for (int o = 16; o; o >>= 1) v += __shfl_down_sync(FULL, v, o);
        if (l == 0) lagS[wp][d] = v;
    }
    __syncwarp();

    // ---- window means via warp prefix scan ----
    {
        float sum0 = lagS[wp][20];
        float val = (l >= 1 && l < WINW) ? (xs[wp][NW - 1 + l] - xs[wp][l - 1]) : 0.f;
        #pragma unroll
        for (int o = 1; o < 32; o <<= 1) {
            float t = __shfl_up_sync(FULL, val, o);
            if (l >= o) val += t;
        }
        if (l < WINW) mwS[wp][l] = (sum0 + val) * (1.f / (float)NW);
    }
    __syncwarp();

    // ---- C via 20 diagonal scans, FULLY UNROLLED with predication ----
    if (l < WINW) {
        const int d = l;
        const float inv = 1.f / (float)(NW - 1);
        float s = lagS[wp][d];
        {
            float cv = (s - (float)NW * mwS[wp][0] * mwS[wp][d]) * inv;
            Cm[wp][0][d] = cv; Cm[wp][d][0] = cv;
        }
        #pragma unroll
        for (int w = 1; w <= 19; ++w) {
            if (w + d < WINW) {
                s += xs[wp][NW - 1 + w] * xs[wp][NW - 1 + w + d]
                   - xs[wp][w - 1]      * xs[wp][w - 1 + d];
                float cv = (s - (float)NW * mwS[wp][w] * mwS[wp][w + d]) * inv;
                Cm[wp][w][w + d] = cv; Cm[wp][w + d][w] = cv;
            }
        }
    }
    __syncwarp();

    // ---- Tg = C*G : lane (wg,c), G column c in registers ----
    {
        const int wg = l >> 3, c = l & 7;
        float Gcol[WINW];
        #pragma unroll
        for (int v = 0; v < WINW; ++v) Gcol[v] = Gs[v * 8 + c];
        #pragma unroll
        for (int t = 0; t < 5; ++t) {
            const int w = wg + 4 * t;
            float s = 0.f;
            #pragma unroll
            for (int v = 0; v < WINW; ++v) s = fmaf(Cm[wp][w][v], Gcol[v], s);
            Tgs[wp][w * 8 + c] = s;
        }
    }
    __syncwarp();

    // ---- S2 = G^T * Tg -> scratch ----
    #pragma unroll
    for (int h = 0; h < 2; ++h) {
        const int e = l + 32 * h;
        const int a = e >> 3, c = e & 7;
        float s = 0.f;
        #pragma unroll
        for (int w = 0; w < WINW; ++w) s = fmaf(Gs[w * 8 + a], Tgs[wp][w * 8 + c], s);
        g_S2[b * 64 + e] = s;
    }
}

// ---------------------------------------------------------------------------
// Jacobi rotation
// ---------------------------------------------------------------------------
__device__ __forceinline__ void jrot(float app, float aqq, float apq,
                                     float& cc, float& ss, float& tt)
{
    float dn = 2.f * apq;
    dn += (dn >= 0.f ? 1e-38f : -1e-38f);
    float th = __fdividef(aqq - app, dn);
    th = fminf(fmaxf(th, -1e18f), 1e18f);
    tt = __fdividef(1.f, fabsf(th) + sqrtf(fmaf(th, th, 1.f)));
    if (th < 0.f) tt = -tt;
    cc = rsqrtf(fmaf(tt, tt, 1.f));
    ss = tt * cc;
}

// ---------------------------------------------------------------------------
// Kernel 2: 4 rows/warp static Jacobi, per-pair dedup, 2 warps/block
// ---------------------------------------------------------------------------
__global__ __launch_bounds__(64)
void radar_eig_kernel(const float* __restrict__ gWl,
                      const float* __restrict__ gbl,
                      float* __restrict__ out, int B)
{
    __shared__ float wls[192];
    __shared__ float bls[3];

    const int tid = threadIdx.x, wp = tid >> 5, l = tid & 31;
    const int g = l >> 3, j = l & 7, gb = g << 3;
    const unsigned FULL = 0xffffffffu;

    for (int i = tid; i < 192; i += 64) wls[i] = gWl[i];
    if (tid < 3) bls[tid] = gbl[tid];
    __syncthreads();

    int row = blockIdx.x * 8 + wp * 4 + g;
    if (row > B - 1) row = B - 1;

    float a[8];
    {
        const float4* p = reinterpret_cast<const float4*>(g_S2 + row * 64 + j * 8);
        float4 q0 = p[0], q1 = p[1];
        a[0]=q0.x; a[1]=q0.y; a[2]=q0.z; a[3]=q0.w;
        a[4]=q1.x; a[5]=q1.y; a[6]=q1.z; a[7]=q1.w;
    }
    float v[8];                              // ROW j of V
    #pragma unroll
    for (int i = 0; i < 8; ++i) v[i] = (i == j) ? 1.f : 0.f;
    float dg = a[j];

    constexpr int P[7][4] = {{0,1,2,3},{0,2,3,4},{0,1,4,5},{0,2,1,6},
                             {0,3,2,1},{0,4,3,1},{0,5,1,2}};
    constexpr int Q[7][4] = {{7,6,5,4},{1,7,6,5},{2,3,7,6},{3,4,5,7},
                             {4,5,6,7},{5,6,7,2},{6,7,4,3}};
    constexpr unsigned PRT[7] = {
        (7u<<0)|(6u<<3)|(5u<<6)|(4u<<9)|(3u<<12)|(2u<<15)|(1u<<18)|(0u<<21),
        (1u<<0)|(0u<<3)|(7u<<6)|(6u<<9)|(5u<<12)|(4u<<15)|(3u<<18)|(2u<<21),
        (2u<<0)|(3u<<3)|(0u<<6)|(1u<<9)|(7u<<12)|(6u<<15)|(5u<<18)|(4u<<21),
        (3u<<0)|(5u<<3)|(4u<<6)|(0u<<9)|(2u<<12)|(1u<<15)|(7u<<18)|(6u<<21),
        (4u<<0)|(7u<<3)|(6u<<6)|(5u<<9)|(0u<<12)|(3u<<15)|(2u<<18)|(1u<<21),
        (5u<<0)|(2u<<3)|(1u<<6)|(7u<<9)|(6u<<12)|(0u<<15)|(4u<<18)|(3u<<21),
        (6u<<0)|(4u<<3)|(3u<<6)|(2u<<9)|(1u<<12)|(7u<<15)|(0u<<18)|(5u<<21)};

    #pragma unroll 1
    for (int sweep = 0; sweep < 4; ++sweep) {
        #pragma unroll
        for (int rr = 0; rr < 7; ++rr) {
            const int prt = (PRT[rr] >> (3 * j)) & 7;
            const bool isp = j < prt;
            const int src = gb + prt;

            float apair = a[0];
            #pragma unroll
            for (int i = 1; i < 8; ++i) if (prt == i) apair = a[i];
            float dgo    = __shfl_sync(FULL, dg,    src);
            float apairo = __shfl_sync(FULL, apair, src);
            float apq = isp ? apairo : apair;
            float app = isp ? dg  : dgo;
            float aqq = isp ? dgo : dg;
            float c, s, t;
            jrot(app, aqq, apq, c, s, t);

            float ck[4], sk[4];
            #pragma unroll
            for (int k = 0; k < 4; ++k) {
                ck[k] = __shfl_sync(FULL, c, gb + P[rr][k]);
                sk[k] = __shfl_sync(FULL, s, gb + P[rr][k]);
            }

            #pragma unroll
            for (int k = 0; k < 4; ++k) {
                const int p = P[rr][k], q = Q[rr][k];
                float tp = a[p], tq = a[q];
                a[p] = fmaf(ck[k], tp, -sk[k] * tq);
                a[q] = fmaf(sk[k], tp,  ck[k] * tq);
                float vp = v[p], vq = v[q];
                v[p] = fmaf(ck[k], vp, -sk[k] * vq);
                v[q] = fmaf(sk[k], vp,  ck[k] * vq);
            }

            float so = isp ? -s : s;
            #pragma unroll
            for (int i = 0; i < 8; ++i) {
                float oa = __shfl_sync(FULL, a[i], src);
                a[i] = fmaf(c, a[i], so * oa);
            }
            dg = fmaf(isp ? -t : t, apq, dg);
        }
    }

    // transpose V (rows -> columns) within the 8-lane group
    #pragma unroll
    for (int m = 1; m < 8; m <<= 1) {
        #pragma unroll
        for (int i = 0; i < 8; ++i) {
            if (i & m) continue;
            const int ip = i | m;
            float send = (j & m) ? v[i] : v[ip];
            float recv = __shfl_xor_sync(FULL, send, m);
            if (j & m) v[i] = recv; else v[ip] = recv;
        }
    }

    // head: out_t = sum_k log(l_k) * v_k^T M_t v_k
    float lg = __logf(fmaxf(dg, 1e-30f));
    float qr[3];
    #pragma unroll
    for (int t = 0; t < 3; ++t) {
        float acc = 0.f;
        #pragma unroll
        for (int i = 0; i < 8; ++i) {
            float wv = 0.f;
            #pragma unroll
            for (int jj = 0; jj < 8; ++jj)
                wv = fmaf(wls[t * 64 + i * 8 + jj], v[jj], wv);
            acc = fmaf(v[i], wv, acc);
        }
        qr[t] = acc * lg;
    }
    #pragma unroll
    for (int t = 0; t < 3; ++t) {
        qr[t] += __shfl_xor_sync(FULL, qr[t], 1);
        qr[t] += __shfl_xor_sync(FULL, qr[t], 2);
        qr[t] += __shfl_xor_sync(FULL, qr[t], 4);
    }
    if (j == 0) {
        out[row * 3 + 0] = qr[0] + bls[0];
        out[row * 3 + 1] = qr[1] + bls[1];
        out[row * 3 + 2] = qr[2] + bls[2];
    }
}

extern "C" void kernel_launch(void* const* d_in, const int* in_sizes, int n_in,
                              void* d_out, int out_size)
{
    const float* x    = (const float*)d_in[0];
    const float* W1   = (const float*)d_in[1];
    const float* W2   = (const float*)d_in[2];
    const float* Wlin = (const float*)d_in[3];
    const float* blin = (const float*)d_in[4];
    float* out = (float*)d_out;

    const int B = in_sizes[0] / TLEN;     // 8192
    radar_cov_kernel<<<B / 4, 128>>>(x, W1, W2);
    radar_eig_kernel<<<B / 8, 64>>>(Wlin, blin, out, B);
}

// round 13
// speedup vs baseline: 1.0474x; 1.0474x over previous
#include <cuda_runtime.h>

// RadarNet R13: two kernels.
// K1: one warp per row; lag reduction = 2 butterfly steps + smem fold.
// K2: 4 rows/warp static Jacobi, per-pair rotation dedup, 4 sweeps
//     (3 sweeps measured FAILING at 5e-3 rel_err in R12 -- clustered spectrum
//     of S2 delays quadratic convergence; 4 sweeps gives 4.1e-5).

namespace {
constexpr int   TLEN = 512;
constexpr int   WINW = 20;
constexpr int   NW   = 493;
constexpr int   MAXB = 8192;
constexpr int   NSWEEP = 4;
}

__device__ float g_S2[MAXB * 64];

// ---------------------------------------------------------------------------
// Kernel 1: covariance + S2, one warp per row, 4 warps/block
// ---------------------------------------------------------------------------
__global__ __launch_bounds__(128)
void radar_cov_kernel(const float* __restrict__ gx,
                      const float* __restrict__ gW1,
                      const float* __restrict__ gW2)
{
    __shared__ float W1s[320], W2s[128], Gs[160];
    __shared__ __align__(16) float xs[4][544];
    __shared__ float Cm[4][WINW][WINW + 1];
    __shared__ float Tgs[4][160];
    __shared__ float partS[4][8][22];
    __shared__ float lagS[4][24];
    __shared__ float mwS[4][WINW];

    const int tid = threadIdx.x, wp = tid >> 5, l = tid & 31;
    const int b = blockIdx.x * 4 + wp;
    const unsigned FULL = 0xffffffffu;

    // ---- per-warp x load ----
    {
        const float4* gx4 = reinterpret_cast<const float4*>(gx + b * TLEN);
        float4* xs4 = reinterpret_cast<float4*>(xs[wp]);
        #pragma unroll
        for (int q = 0; q < 4; ++q) xs4[l + 32 * q] = gx4[l + 32 * q];
        if (l < 8) xs4[128 + l] = make_float4(0.f, 0.f, 0.f, 0.f);
    }

    // ---- block-cooperative weights + G = W1@W2 ----
    for (int i = tid; i < 320; i += 128) W1s[i] = gW1[i];
    if (tid < 128) W2s[tid] = gW2[tid];
    __syncthreads();
    for (int t = tid; t < 160; t += 128) {
        int w = t >> 3, c = t & 7;
        float s = 0.f;
        #pragma unroll
        for (int k = 0; k < 16; ++k) s = fmaf(W1s[w * 16 + k], W2s[k * 8 + c], s);
        Gs[t] = s;
    }
    __syncthreads();

    // ---- lag accumulation: lane l handles n in [16l, 16l+16) ----
    float xv[36];
    {
        const float4* base = reinterpret_cast<const float4*>(xs[wp] + 16 * l);
        #pragma unroll
        for (int q = 0; q < 9; ++q) {
            float4 t = base[q];
            xv[4*q+0] = t.x; xv[4*q+1] = t.y; xv[4*q+2] = t.z; xv[4*q+3] = t.w;
        }
    }
    float acc[21];
    #pragma unroll
    for (int d = 0; d < 21; ++d) acc[d] = 0.f;
    {
        const int nb = 16 * l;
        #pragma unroll
        for (int k = 0; k < 16; ++k) {
            if (nb + k < NW) {
                float xk = xv[k];
                #pragma unroll
                for (int d = 0; d < WINW; ++d) acc[d] = fmaf(xk, xv[k + d], acc[d]);
                acc[20] += xk;
            }
        }
    }
    // 2-step butterfly -> partials in lanes 0-7, smem fold by 21 lanes
    #pragma unroll
    for (int d = 0; d < 21; ++d) {
        acc[d] += __shfl_down_sync(FULL, acc[d], 16);
        acc[d] += __shfl_down_sync(FULL, acc[d], 8);
    }
    if (l < 8) {
        #pragma unroll
        for (int d = 0; d < 21; ++d) partS[wp][l][d] = acc[d];
    }
    __syncwarp();
    if (l < 21) {
        float s = 0.f;
        #pragma unroll
        for (int k = 0; k < 8; ++k) s += partS[wp][k][l];
        lagS[wp][l] = s;
    }
    __syncwarp();

    // ---- window means via warp prefix scan ----
    {
        float sum0 = lagS[wp][20];
        float val = (l >= 1 && l < WINW) ? (xs[wp][NW - 1 + l] - xs[wp][l - 1]) : 0.f;
        #pragma unroll
        for (int o = 1; o < 32; o <<= 1) {
            float t = __shfl_up_sync(FULL, val, o);
            if (l >= o) val += t;
        }
        if (l < WINW) mwS[wp][l] = (sum0 + val) * (1.f / (float)NW);
    }
    __syncwarp();

    // ---- C via 20 diagonal scans (unrolled, predicated) ----
    if (l < WINW) {
        const int d = l;
        const float inv = 1.f / (float)(NW - 1);
        float s = lagS[wp][d];
        {
            float cv = (s - (float)NW * mwS[wp][0] * mwS[wp][d]) * inv;
            Cm[wp][0][d] = cv; Cm[wp][d][0] = cv;
        }
        #pragma unroll
        for (int w = 1; w <= 19; ++w) {
            if (w + d < WINW) {
                s += xs[wp][NW - 1 + w] * xs[wp][NW - 1 + w + d]
                   - xs[wp][w - 1]      * xs[wp][w - 1 + d];
                float cv = (s - (float)NW * mwS[wp][w] * mwS[wp][w + d]) * inv;
                Cm[wp][w][w + d] = cv; Cm[wp][w + d][w] = cv;
            }
        }
    }
    __syncwarp();

    // ---- Tg = C*G ----
    {
        const int wg = l >> 3, c = l & 7;
        float Gcol[WINW];
        #pragma unroll
        for (int v = 0; v < WINW; ++v) Gcol[v] = Gs[v * 8 + c];
        #pragma unroll
        for (int t = 0; t < 5; ++t) {
            const int w = wg + 4 * t;
            float s = 0.f;
            #pragma unroll
            for (int v = 0; v < WINW; ++v) s = fmaf(Cm[wp][w][v], Gcol[v], s);
            Tgs[wp][w * 8 + c] = s;
        }
    }
    __syncwarp();

    // ---- S2 = G^T * Tg -> scratch ----
    #pragma unroll
    for (int h = 0; h < 2; ++h) {
        const int e = l + 32 * h;
        const int a = e >> 3, c = e & 7;
        float s = 0.f;
        #pragma unroll
        for (int w = 0; w < WINW; ++w) s = fmaf(Gs[w * 8 + a], Tgs[wp][w * 8 + c], s);
        g_S2[b * 64 + e] = s;
    }
}

// ---------------------------------------------------------------------------
// Jacobi rotation
// ---------------------------------------------------------------------------
__device__ __forceinline__ void jrot(float app, float aqq, float apq,
                                     float& cc, float& ss, float& tt)
{
    float dn = 2.f * apq;
    dn += (dn >= 0.f ? 1e-38f : -1e-38f);
    float th = __fdividef(aqq - app, dn);
    th = fminf(fmaxf(th, -1e18f), 1e18f);
    tt = __fdividef(1.f, fabsf(th) + sqrtf(fmaf(th, th, 1.f)));
    if (th < 0.f) tt = -tt;
    cc = rsqrtf(fmaf(tt, tt, 1.f));
    ss = tt * cc;
}

// ---------------------------------------------------------------------------
// Kernel 2: 4 rows/warp static Jacobi, per-pair dedup, 4 sweeps
// ---------------------------------------------------------------------------
__global__ __launch_bounds__(256)
void radar_eig_kernel(const float* __restrict__ gWl,
                      const float* __restrict__ gbl,
                      float* __restrict__ out, int B)
{
    __shared__ float wls[192];
    __shared__ float bls[3];

    const int tid = threadIdx.x, wp = tid >> 5, l = tid & 31;
    const int g = l >> 3, j = l & 7, gb = g << 3;
    const unsigned FULL = 0xffffffffu;

    for (int i = tid; i < 192; i += 256) wls[i] = gWl[i];
    if (tid < 3) bls[tid] = gbl[tid];
    __syncthreads();

    int row = blockIdx.x * 32 + wp * 4 + g;
    if (row > B - 1) row = B - 1;

    float a[8];
    {
        const float4* p = reinterpret_cast<const float4*>(g_S2 + row * 64 + j * 8);
        float4 q0 = p[0], q1 = p[1];
        a[0]=q0.x; a[1]=q0.y; a[2]=q0.z; a[3]=q0.w;
        a[4]=q1.x; a[5]=q1.y; a[6]=q1.z; a[7]=q1.w;
    }
    float v[8];                              // ROW j of V
    #pragma unroll
    for (int i = 0; i < 8; ++i) v[i] = (i == j) ? 1.f : 0.f;
    float dg = a[j];

    constexpr int P[7][4] = {{0,1,2,3},{0,2,3,4},{0,1,4,5},{0,2,1,6},
                             {0,3,2,1},{0,4,3,1},{0,5,1,2}};
    constexpr int Q[7][4] = {{7,6,5,4},{1,7,6,5},{2,3,7,6},{3,4,5,7},
                             {4,5,6,7},{5,6,7,2},{6,7,4,3}};
    constexpr unsigned PRT[7] = {
        (7u<<0)|(6u<<3)|(5u<<6)|(4u<<9)|(3u<<12)|(2u<<15)|(1u<<18)|(0u<<21),
        (1u<<0)|(0u<<3)|(7u<<6)|(6u<<9)|(5u<<12)|(4u<<15)|(3u<<18)|(2u<<21),
        (2u<<0)|(3u<<3)|(0u<<6)|(1u<<9)|(7u<<12)|(6u<<15)|(5u<<18)|(4u<<21),
        (3u<<0)|(5u<<3)|(4u<<6)|(0u<<9)|(2u<<12)|(1u<<15)|(7u<<18)|(6u<<21),
        (4u<<0)|(7u<<3)|(6u<<6)|(5u<<9)|(0u<<12)|(3u<<15)|(2u<<18)|(1u<<21),
        (5u<<0)|(2u<<3)|(1u<<6)|(7u<<9)|(6u<<12)|(0u<<15)|(4u<<18)|(3u<<21),
        (6u<<0)|(4u<<3)|(3u<<6)|(2u<<9)|(1u<<12)|(7u<<15)|(0u<<18)|(5u<<21)};

    #pragma unroll 1
    for (int sweep = 0; sweep < NSWEEP; ++sweep) {
        #pragma unroll
        for (int rr = 0; rr < 7; ++rr) {
            const int prt = (PRT[rr] >> (3 * j)) & 7;
            const bool isp = j < prt;
            const int src = gb + prt;

            float apair = a[0];
            #pragma unroll
            for (int i = 1; i < 8; ++i) if (prt == i) apair = a[i];
            float dgo    = __shfl_sync(FULL, dg,    src);
            float apairo = __shfl_sync(FULL, apair, src);
            float apq = isp ? apairo : apair;
            float app = isp ? dg  : dgo;
            float aqq = isp ? dgo : dg;
            float c, s, t;
            jrot(app, aqq, apq, c, s, t);

            float ck[4], sk[4];
            #pragma unroll
            for (int k = 0; k < 4; ++k) {
                ck[k] = __shfl_sync(FULL, c, gb + P[rr][k]);
                sk[k] = __shfl_sync(FULL, s, gb + P[rr][k]);
            }

            #pragma unroll
            for (int k = 0; k < 4; ++k) {
                const int p = P[rr][k], q = Q[rr][k];
                float tp = a[p], tq = a[q];
                a[p] = fmaf(ck[k], tp, -sk[k] * tq);
                a[q] = fmaf(sk[k], tp,  ck[k] * tq);
                float vp = v[p], vq = v[q];
                v[p] = fmaf(ck[k], vp, -sk[k] * vq);
                v[q] = fmaf(sk[k], vp,  ck[k] * vq);
            }

            float so = isp ? -s : s;
            #pragma unroll
            for (int i = 0; i < 8; ++i) {
                float oa = __shfl_sync(FULL, a[i], src);
                a[i] = fmaf(c, a[i], so * oa);
            }
            dg = fmaf(isp ? -t : t, apq, dg);
        }
    }

    // transpose V (rows -> columns) within the 8-lane group
    #pragma unroll
    for (int m = 1; m < 8; m <<= 1) {
        #pragma unroll
        for (int i = 0; i < 8; ++i) {
            if (i & m) continue;
            const int ip = i | m;
            float send = (j & m) ? v[i] : v[ip];
            float recv = __shfl_xor_sync(FULL, send, m);
            if (j & m) v[i] = recv; else v[ip] = recv;
        }
    }

    // head: out_t = sum_k log(l_k) * v_k^T M_t v_k
    float lg = __logf(fmaxf(dg, 1e-30f));
    float qr[3];
    #pragma unroll
    for (int t = 0; t < 3; ++t) {
        float acc = 0.f;
        #pragma unroll
        for (int i = 0; i < 8; ++i) {
            float wv = 0.f;
            #pragma unroll
            for (int jj = 0; jj < 8; ++jj)
                wv = fmaf(wls[t * 64 + i * 8 + jj], v[jj], wv);
            acc = fmaf(v[i], wv, acc);
        }
        qr[t] = acc * lg;
    }
    #pragma unroll
    for (int t = 0; t < 3; ++t) {
        qr[t] += __shfl_xor_sync(FULL, qr[t], 1);
        qr[t] += __shfl_xor_sync(FULL, qr[t], 2);
        qr[t] += __shfl_xor_sync(FULL, qr[t], 4);
    }
    if (j == 0) {
        out[row * 3 + 0] = qr[0] + bls[0];
        out[row * 3 + 1] = qr[1] + bls[1];
        out[row * 3 + 2] = qr[2] + bls[2];
    }
}

extern "C" void kernel_launch(void* const* d_in, const int* in_sizes, int n_in,
                              void* d_out, int out_size)
{
    const float* x    = (const float*)d_in[0];
    const float* W1   = (const float*)d_in[1];
    const float* W2   = (const float*)d_in[2];
    const float* Wlin = (const float*)d_in[3];
    const float* blin = (const float*)d_in[4];
    float* out = (float*)d_out;

    const int B = in_sizes[0] / TLEN;     // 8192
    radar_cov_kernel<<<B / 4, 128>>>(x, W1, W2);
    radar_eig_kernel<<<(B + 31) / 32, 256>>>(Wlin, blin, out, B);
}